// round 4
// baseline (speedup 1.0000x reference)
#include <cuda_runtime.h>
#include <math.h>

typedef unsigned long long u64;

// ---------------------------------------------------------------------------
// Problem constants
// ---------------------------------------------------------------------------
#define BB 4
#define LL 1024
#define DD 1024
#define HH 16
#define HD 64
#define II 3280
#define NROWS (BB * LL)
#define EPSV 1e-5f

#define SZ_D ((size_t)NROWS * DD)
#define SZ_I ((size_t)NROWS * II)
__device__ float g_scratch[9 * SZ_D + 2 * SZ_I];

// packed fp32x2 helpers (sm_103a FFMA2)
__device__ __forceinline__ u64 pack_dup(float a) {
    u64 r;
    asm("mov.b64 %0, {%1, %1};" : "=l"(r) : "f"(a));
    return r;
}
__device__ __forceinline__ void fma2(u64& acc, u64 a, u64 b) {
    asm("fma.rn.f32x2 %0, %1, %2, %0;" : "+l"(acc) : "l"(a), "l"(b));
}
__device__ __forceinline__ void unpack2(float& lo, float& hi, u64 v) {
    asm("mov.b64 {%0, %1}, %2;" : "=f"(lo), "=f"(hi) : "l"(v));
}

// ---------------------------------------------------------------------------
// RMSNorm
// ---------------------------------------------------------------------------
template <int W, int T>
__global__ void rmsnorm_k(const float* __restrict__ in,
                          const float* __restrict__ w,
                          const float* __restrict__ resid,
                          float* __restrict__ out)
{
    constexpr int PER = W / T;
    const size_t row = blockIdx.x;
    const float* xr = in + row * (size_t)W;
    float vals[PER];
    float ss = 0.f;
#pragma unroll
    for (int i = 0; i < PER; i++) {
        float vv = xr[threadIdx.x + i * T];
        vv = fminf(fmaxf(vv, -10000.f), 10000.f);
        vals[i] = vv;
        ss += vv * vv;
    }
    __shared__ float red[T];
    red[threadIdx.x] = ss;
    __syncthreads();
#pragma unroll
    for (int s = T / 2; s > 0; s >>= 1) {
        if (threadIdx.x < s) red[threadIdx.x] += red[threadIdx.x + s];
        __syncthreads();
    }
    const float mean = red[0] / (float)W;
    const float inv = 1.f / sqrtf(fmaxf(mean, EPSV) + EPSV);
#pragma unroll
    for (int i = 0; i < PER; i++) {
        const int c = threadIdx.x + i * T;
        float o = vals[i] * inv * w[c];
        if (!isfinite(o)) o = 0.f;
        if (resid) o += resid[row * (size_t)W + c];
        out[row * (size_t)W + c] = o;
    }
}

// ---------------------------------------------------------------------------
// SGEMM (NT): C[n,m] = sum_k A[n,k]*B[m,k] + bias[m]
// 128x128 tile, BK=8, 256 threads, 8x8/thread.
// Double-buffered smem, register prefetch, packed f32x2 FMA mainloop.
// ---------------------------------------------------------------------------
__global__ void __launch_bounds__(256, 2)
gemm_nt_bias(const float* __restrict__ A, const float* __restrict__ B,
             const float* __restrict__ bias, float* __restrict__ C,
             int N, int M, int K)
{
    __shared__ float As[2][8][128];
    __shared__ float Bs[2][8][128];

    const int tid  = threadIdx.x;
    const int lrow = tid >> 1;
    const int lcol = (tid & 1) << 2;
    const size_t arow = (size_t)blockIdx.y * 128 + lrow;
    const size_t brow = (size_t)blockIdx.x * 128 + lrow;
    const bool bval = brow < (size_t)M;

    const float* Ap = A + arow * (size_t)K + lcol;
    const float* Bp = B + brow * (size_t)K + lcol;

    const int ty = tid >> 4;
    const int tx = tid & 15;

    // packed accumulators: acc2[i][p] = (C[i][2p], C[i][2p+1])
    u64 acc2[8][4];
#pragma unroll
    for (int i = 0; i < 8; i++)
#pragma unroll
        for (int p = 0; p < 4; p++) acc2[i][p] = 0ull;

    // Preload first tile
    {
        float4 a4 = *(const float4*)(Ap);
        float4 b4 = bval ? *(const float4*)(Bp) : make_float4(0.f, 0.f, 0.f, 0.f);
        As[0][lcol + 0][lrow] = a4.x; As[0][lcol + 1][lrow] = a4.y;
        As[0][lcol + 2][lrow] = a4.z; As[0][lcol + 3][lrow] = a4.w;
        Bs[0][lcol + 0][lrow] = b4.x; Bs[0][lcol + 1][lrow] = b4.y;
        Bs[0][lcol + 2][lrow] = b4.z; Bs[0][lcol + 3][lrow] = b4.w;
    }
    __syncthreads();

    int buf = 0;
    for (int k0 = 8; k0 < K; k0 += 8) {
        float4 a4n = *(const float4*)(Ap + k0);
        float4 b4n = bval ? *(const float4*)(Bp + k0) : make_float4(0.f, 0.f, 0.f, 0.f);

#pragma unroll
        for (int kk = 0; kk < 8; kk++) {
            const float4 a0 = *(const float4*)&As[buf][kk][ty * 8];
            const float4 a1 = *(const float4*)&As[buf][kk][ty * 8 + 4];
            const longlong2 bb0 = *(const longlong2*)&Bs[buf][kk][tx * 8];
            const longlong2 bb1 = *(const longlong2*)&Bs[buf][kk][tx * 8 + 4];
            const u64 b2[4] = {(u64)bb0.x, (u64)bb0.y, (u64)bb1.x, (u64)bb1.y};
            const float ar[8] = {a0.x, a0.y, a0.z, a0.w, a1.x, a1.y, a1.z, a1.w};
#pragma unroll
            for (int i = 0; i < 8; i++) {
                const u64 a2 = pack_dup(ar[i]);
                fma2(acc2[i][0], a2, b2[0]);
                fma2(acc2[i][1], a2, b2[1]);
                fma2(acc2[i][2], a2, b2[2]);
                fma2(acc2[i][3], a2, b2[3]);
            }
        }

        const int nb = buf ^ 1;
        As[nb][lcol + 0][lrow] = a4n.x; As[nb][lcol + 1][lrow] = a4n.y;
        As[nb][lcol + 2][lrow] = a4n.z; As[nb][lcol + 3][lrow] = a4n.w;
        Bs[nb][lcol + 0][lrow] = b4n.x; Bs[nb][lcol + 1][lrow] = b4n.y;
        Bs[nb][lcol + 2][lrow] = b4n.z; Bs[nb][lcol + 3][lrow] = b4n.w;
        __syncthreads();
        buf = nb;
    }

#pragma unroll
    for (int kk = 0; kk < 8; kk++) {
        const float4 a0 = *(const float4*)&As[buf][kk][ty * 8];
        const float4 a1 = *(const float4*)&As[buf][kk][ty * 8 + 4];
        const longlong2 bb0 = *(const longlong2*)&Bs[buf][kk][tx * 8];
        const longlong2 bb1 = *(const longlong2*)&Bs[buf][kk][tx * 8 + 4];
        const u64 b2[4] = {(u64)bb0.x, (u64)bb0.y, (u64)bb1.x, (u64)bb1.y};
        const float ar[8] = {a0.x, a0.y, a0.z, a0.w, a1.x, a1.y, a1.z, a1.w};
#pragma unroll
        for (int i = 0; i < 8; i++) {
            const u64 a2 = pack_dup(ar[i]);
            fma2(acc2[i][0], a2, b2[0]);
            fma2(acc2[i][1], a2, b2[1]);
            fma2(acc2[i][2], a2, b2[2]);
            fma2(acc2[i][3], a2, b2[3]);
        }
    }

    // Epilogue
    const int colbase = blockIdx.x * 128 + tx * 8;
    const float4 bi0 = (colbase < M) ? *(const float4*)&bias[colbase]
                                     : make_float4(0.f, 0.f, 0.f, 0.f);
    const float4 bi1 = (colbase + 4 < M) ? *(const float4*)&bias[colbase + 4]
                                         : make_float4(0.f, 0.f, 0.f, 0.f);
#pragma unroll
    for (int i = 0; i < 8; i++) {
        const size_t row = (size_t)blockIdx.y * 128 + ty * 8 + i;
        float c0, c1, c2, c3, c4, c5, c6, c7;
        unpack2(c0, c1, acc2[i][0]);
        unpack2(c2, c3, acc2[i][1]);
        unpack2(c4, c5, acc2[i][2]);
        unpack2(c6, c7, acc2[i][3]);
        if (colbase < M) {
            float4 o0 = make_float4(c0 + bi0.x, c1 + bi0.y, c2 + bi0.z, c3 + bi0.w);
            *(float4*)&C[row * (size_t)M + colbase] = o0;
        }
        if (colbase + 4 < M) {
            float4 o1 = make_float4(c4 + bi1.x, c5 + bi1.y, c6 + bi1.z, c7 + bi1.w);
            *(float4*)&C[row * (size_t)M + colbase + 4] = o1;
        }
    }
}

// ---------------------------------------------------------------------------
// Tiled sliding-window attention (flash style).
// ---------------------------------------------------------------------------
#define ATT_SMEM_FLOATS (4 * 64 * 64 + 3 * 64)

__global__ void __launch_bounds__(256)
attn_tile_kernel(const float* __restrict__ q, const float* __restrict__ k,
                 const float* __restrict__ v, float* __restrict__ o,
                 const int* __restrict__ winp)
{
    extern __shared__ float sm[];
    float* Qs  = sm;
    float* Kst = Qs + 64 * 64;
    float* Vs  = Kst + 64 * 64;
    float* Ss  = Vs + 64 * 64;
    float* m_s = Ss + 64 * 64;
    float* l_s = m_s + 64;
    float* sc_s = l_s + 64;

    const int q0 = blockIdx.x * 64;
    const int h  = blockIdx.y;
    const int b  = blockIdx.z;
    const int tid = threadIdx.x;
    const int win = *winp;

    const size_t base_q = ((size_t)(b * LL + q0)) * DD + h * HD;

    for (int i = tid; i < 1024; i += 256) {
        const int r = i >> 4;
        const int d4 = (i & 15) << 2;
        *(float4*)&Qs[r * 64 + d4] =
            *(const float4*)&q[base_q + (size_t)r * DD + d4];
    }
    if (tid < 64) { m_s[tid] = -INFINITY; l_s[tid] = 0.f; }

    const int ty = tid >> 4;
    const int tx = tid & 15;
    float accO[4][4];
#pragma unroll
    for (int i = 0; i < 4; i++)
#pragma unroll
        for (int j = 0; j < 4; j++) accO[i][j] = 0.f;

    int lo = q0 - win + 1;
    if (lo < 0) lo = 0;
    const int kt0 = lo >> 6;
    const int kt1 = q0 >> 6;

    __syncthreads();

    for (int kt = kt0; kt <= kt1; kt++) {
        const int j0 = kt << 6;
        const size_t base_k = ((size_t)(b * LL + j0)) * DD + h * HD;

        for (int i = tid; i < 1024; i += 256) {
            const int r = i >> 4;
            const int d4 = (i & 15) << 2;
            const float4 kv = *(const float4*)&k[base_k + (size_t)r * DD + d4];
            Kst[(d4 + 0) * 64 + r] = kv.x;
            Kst[(d4 + 1) * 64 + r] = kv.y;
            Kst[(d4 + 2) * 64 + r] = kv.z;
            Kst[(d4 + 3) * 64 + r] = kv.w;
            *(float4*)&Vs[r * 64 + d4] =
                *(const float4*)&v[base_k + (size_t)r * DD + d4];
        }
        __syncthreads();

        float accS[4][4];
#pragma unroll
        for (int i = 0; i < 4; i++)
#pragma unroll
            for (int j = 0; j < 4; j++) accS[i][j] = 0.f;

        for (int d = 0; d < 64; d += 4) {
            float4 qv[4];
#pragma unroll
            for (int i = 0; i < 4; i++)
                qv[i] = *(const float4*)&Qs[(ty * 4 + i) * 64 + d];
#pragma unroll
            for (int dd = 0; dd < 4; dd++) {
                const float4 kv = *(const float4*)&Kst[(d + dd) * 64 + tx * 4];
#pragma unroll
                for (int i = 0; i < 4; i++) {
                    const float qq = ((const float*)&qv[i])[dd];
                    accS[i][0] = fmaf(qq, kv.x, accS[i][0]);
                    accS[i][1] = fmaf(qq, kv.y, accS[i][1]);
                    accS[i][2] = fmaf(qq, kv.z, accS[i][2]);
                    accS[i][3] = fmaf(qq, kv.w, accS[i][3]);
                }
            }
        }

#pragma unroll
        for (int i = 0; i < 4; i++) {
            const int qi = q0 + ty * 4 + i;
#pragma unroll
            for (int j = 0; j < 4; j++) {
                const int jj = j0 + tx * 4 + j;
                const bool ok = (jj <= qi) && (qi - jj < win);
                Ss[(ty * 4 + i) * 64 + tx * 4 + j] =
                    ok ? accS[i][j] * 0.125f : -INFINITY;
            }
        }
        __syncthreads();

        {
            const int row = tid >> 2;
            const int part = tid & 3;
            float* srow = &Ss[row * 64 + part * 16];
            float tm = -INFINITY;
#pragma unroll
            for (int c = 0; c < 16; c++) tm = fmaxf(tm, srow[c]);
            tm = fmaxf(tm, __shfl_xor_sync(0xffffffffu, tm, 1));
            tm = fmaxf(tm, __shfl_xor_sync(0xffffffffu, tm, 2));

            const float mold = m_s[row];
            const float nm = fmaxf(mold, tm);
            float scale;
            float psum = 0.f;
            if (nm == -INFINITY) {
                scale = 1.f;
#pragma unroll
                for (int c = 0; c < 16; c++) srow[c] = 0.f;
            } else {
                scale = expf(mold - nm);
#pragma unroll
                for (int c = 0; c < 16; c++) {
                    const float p = expf(srow[c] - nm);
                    srow[c] = p;
                    psum += p;
                }
            }
            psum += __shfl_xor_sync(0xffffffffu, psum, 1);
            psum += __shfl_xor_sync(0xffffffffu, psum, 2);
            if (part == 0) {
                m_s[row] = nm;
                l_s[row] = l_s[row] * scale + psum;
                sc_s[row] = scale;
            }
        }
        __syncthreads();

#pragma unroll
        for (int i = 0; i < 4; i++) {
            const float s = sc_s[ty * 4 + i];
#pragma unroll
            for (int j = 0; j < 4; j++) accO[i][j] *= s;
        }
        for (int kk = 0; kk < 64; kk += 4) {
            float4 pv[4];
#pragma unroll
            for (int i = 0; i < 4; i++)
                pv[i] = *(const float4*)&Ss[(ty * 4 + i) * 64 + kk];
#pragma unroll
            for (int dd = 0; dd < 4; dd++) {
                const float4 vv = *(const float4*)&Vs[(kk + dd) * 64 + tx * 4];
#pragma unroll
                for (int i = 0; i < 4; i++) {
                    const float pp = ((const float*)&pv[i])[dd];
                    accO[i][0] = fmaf(pp, vv.x, accO[i][0]);
                    accO[i][1] = fmaf(pp, vv.y, accO[i][1]);
                    accO[i][2] = fmaf(pp, vv.z, accO[i][2]);
                    accO[i][3] = fmaf(pp, vv.w, accO[i][3]);
                }
            }
        }
        __syncthreads();
    }

#pragma unroll
    for (int i = 0; i < 4; i++) {
        const int r = ty * 4 + i;
        const float linv = 1.f / l_s[r];
#pragma unroll
        for (int j = 0; j < 4; j++) {
            float outv = accO[i][j] * linv;
            if (!isfinite(outv)) outv = 0.f;
            o[((size_t)(b * LL + q0 + r)) * DD + h * HD + tx * 4 + j] = outv;
        }
    }
}

// ---------------------------------------------------------------------------
// g = silu(z1) * z3
// ---------------------------------------------------------------------------
__global__ void silu_mul_k(const float* __restrict__ z1,
                           const float* __restrict__ z3,
                           float* __restrict__ g, size_t n)
{
    size_t i = (size_t)blockIdx.x * blockDim.x + threadIdx.x;
    if (i < n) {
        float a = z1[i];
        float sv = a / (1.f + expf(-a));
        g[i] = sv * z3[i];
    }
}

// ---------------------------------------------------------------------------
// Launch
// ---------------------------------------------------------------------------
extern "C" void kernel_launch(void* const* d_in, const int* in_sizes, int n_in,
                              void* d_out, int out_size)
{
    const float* x    = (const float*)d_in[0];
    const float* wq_w = (const float*)d_in[1];
    const float* wq_b = (const float*)d_in[2];
    const float* wk_w = (const float*)d_in[3];
    const float* wk_b = (const float*)d_in[4];
    const float* wv_w = (const float*)d_in[5];
    const float* wv_b = (const float*)d_in[6];
    const float* wo_w = (const float*)d_in[7];
    const float* wo_b = (const float*)d_in[8];
    const float* q_nw = (const float*)d_in[9];
    const float* k_nw = (const float*)d_in[10];
    const float* s_nw = (const float*)d_in[11];
    const float* sp_nw= (const float*)d_in[12];
    const float* f_nw = (const float*)d_in[13];
    const float* fp_nw= (const float*)d_in[14];
    const float* w1_w = (const float*)d_in[15];
    const float* w1_b = (const float*)d_in[16];
    const float* w2_w = (const float*)d_in[17];
    const float* w2_b = (const float*)d_in[18];
    const float* w3_w = (const float*)d_in[19];
    const float* w3_b = (const float*)d_in[20];
    const int*   winp = (const int*)d_in[21];

    float* base = nullptr;
    cudaGetSymbolAddress((void**)&base, g_scratch);
    float* xn   = base + 0 * SZ_D;
    float* q    = base + 1 * SZ_D;
    float* k    = base + 2 * SZ_D;
    float* v    = base + 3 * SZ_D;
    float* attn = base + 4 * SZ_D;
    float* a    = base + 5 * SZ_D;
    float* h    = base + 6 * SZ_D;
    float* hn   = base + 7 * SZ_D;
    float* f    = base + 8 * SZ_D;
    float* z1   = base + 9 * SZ_D;
    float* z3   = base + 9 * SZ_D + SZ_I;

    float* out = (float*)d_out;

    rmsnorm_k<DD, 256><<<NROWS, 256>>>(x, s_nw, nullptr, xn);

    {
        dim3 grid(DD / 128, NROWS / 128);
        gemm_nt_bias<<<grid, 256>>>(xn, wq_w, wq_b, q, NROWS, DD, DD);
        gemm_nt_bias<<<grid, 256>>>(xn, wk_w, wk_b, k, NROWS, DD, DD);
        gemm_nt_bias<<<grid, 256>>>(xn, wv_w, wv_b, v, NROWS, DD, DD);
    }

    rmsnorm_k<HD, 64><<<NROWS * HH, 64>>>(q, q_nw, nullptr, q);
    rmsnorm_k<HD, 64><<<NROWS * HH, 64>>>(k, k_nw, nullptr, k);

    {
        const size_t smem_bytes = (size_t)ATT_SMEM_FLOATS * sizeof(float);
        cudaFuncSetAttribute(attn_tile_kernel,
                             cudaFuncAttributeMaxDynamicSharedMemorySize,
                             (int)smem_bytes);
        dim3 grid(LL / 64, HH, BB);
        attn_tile_kernel<<<grid, 256, smem_bytes>>>(q, k, v, attn, winp);
    }

    {
        dim3 grid(DD / 128, NROWS / 128);
        gemm_nt_bias<<<grid, 256>>>(attn, wo_w, wo_b, a, NROWS, DD, DD);
    }

    rmsnorm_k<DD, 256><<<NROWS, 256>>>(a, sp_nw, x, h);
    rmsnorm_k<DD, 256><<<NROWS, 256>>>(h, f_nw, nullptr, hn);

    {
        dim3 grid((II + 127) / 128, NROWS / 128);
        gemm_nt_bias<<<grid, 256>>>(hn, w1_w, w1_b, z1, NROWS, II, DD);
        gemm_nt_bias<<<grid, 256>>>(hn, w3_w, w3_b, z3, NROWS, II, DD);
    }

    {
        size_t n = (size_t)NROWS * II;
        silu_mul_k<<<(int)((n + 255) / 256), 256>>>(z1, z3, z1, n);
    }

    {
        dim3 grid(DD / 128, NROWS / 128);
        gemm_nt_bias<<<grid, 256>>>(z1, w2_w, w2_b, f, NROWS, DD, II);
    }

    rmsnorm_k<DD, 256><<<NROWS, 256>>>(f, fp_nw, h, out);
}

// round 5
// speedup vs baseline: 2.2924x; 2.2924x over previous
#include <cuda_runtime.h>
#include <cuda_bf16.h>
#include <math.h>
#include <stdint.h>

typedef __nv_bfloat16 bf16;

// ---------------------------------------------------------------------------
// Problem constants
// ---------------------------------------------------------------------------
#define BB 4
#define LL 1024
#define DD 1024
#define HH 16
#define HD 64
#define II 3280
#define IIP 3296               // II padded to multiple of 32
#define NROWS (BB * LL)        // 4096
#define EPSV 1e-5f

#define SZ_D ((size_t)NROWS * DD)
#define SZ_I ((size_t)NROWS * II)

// fp32 scratch: q,k,v,a,h,f + z1,z3
__device__ float g_scratch[6 * SZ_D + 2 * SZ_I];

// bf16 scratch (hi/lo pairs)
#define BSZ_ACT ((size_t)NROWS * DD)        // 4.19M
#define BSZ_G   ((size_t)NROWS * IIP)       // 13.5M
#define BSZ_W   ((size_t)1024 * IIP)        // 3.375M (max weight tile)
__device__ bf16 g_bscratch[6 * BSZ_ACT + 2 * BSZ_G + 2 * BSZ_W];

// ---------------------------------------------------------------------------
// helpers
// ---------------------------------------------------------------------------
__device__ __forceinline__ void split_f32(float v, bf16& hi, bf16& lo) {
    hi = __float2bfloat16(v);
    lo = __float2bfloat16(v - __bfloat162float(hi));
}

__device__ __forceinline__ void cpa16(bf16* dst, const bf16* src, bool valid) {
    uint32_t d = (uint32_t)__cvta_generic_to_shared(dst);
    int sz = valid ? 16 : 0;
    asm volatile("cp.async.ca.shared.global [%0], [%1], 16, %2;\n"
                 :: "r"(d), "l"(src), "r"(sz));
}
__device__ __forceinline__ void cpa_commit() {
    asm volatile("cp.async.commit_group;\n" ::: "memory");
}
__device__ __forceinline__ void cpa_wait_all() {
    asm volatile("cp.async.wait_group 0;\n" ::: "memory");
}

__device__ __forceinline__ void ldm4(uint32_t* r, uint32_t addr) {
    asm volatile("ldmatrix.sync.aligned.m8n8.x4.shared.b16 {%0,%1,%2,%3}, [%4];\n"
                 : "=r"(r[0]), "=r"(r[1]), "=r"(r[2]), "=r"(r[3]) : "r"(addr));
}

__device__ __forceinline__ void mma16816(float* d, const uint32_t* a, const uint32_t* b) {
    asm volatile(
        "mma.sync.aligned.m16n8k16.row.col.f32.bf16.bf16.f32 "
        "{%0,%1,%2,%3}, {%4,%5,%6,%7}, {%8,%9}, {%0,%1,%2,%3};\n"
        : "+f"(d[0]), "+f"(d[1]), "+f"(d[2]), "+f"(d[3])
        : "r"(a[0]), "r"(a[1]), "r"(a[2]), "r"(a[3]), "r"(b[0]), "r"(b[1]));
}

// ---------------------------------------------------------------------------
// RMSNorm (fp32 out, optional residual)
// ---------------------------------------------------------------------------
template <int W, int T>
__global__ void rmsnorm_k(const float* __restrict__ in,
                          const float* __restrict__ w,
                          const float* __restrict__ resid,
                          float* __restrict__ out)
{
    constexpr int PER = W / T;
    const size_t row = blockIdx.x;
    const float* xr = in + row * (size_t)W;
    float vals[PER];
    float ss = 0.f;
#pragma unroll
    for (int i = 0; i < PER; i++) {
        float vv = xr[threadIdx.x + i * T];
        vv = fminf(fmaxf(vv, -10000.f), 10000.f);
        vals[i] = vv;
        ss += vv * vv;
    }
    __shared__ float red[T];
    red[threadIdx.x] = ss;
    __syncthreads();
#pragma unroll
    for (int s = T / 2; s > 0; s >>= 1) {
        if (threadIdx.x < s) red[threadIdx.x] += red[threadIdx.x + s];
        __syncthreads();
    }
    const float mean = red[0] / (float)W;
    const float inv = 1.f / sqrtf(fmaxf(mean, EPSV) + EPSV);
#pragma unroll
    for (int i = 0; i < PER; i++) {
        const int c = threadIdx.x + i * T;
        float o = vals[i] * inv * w[c];
        if (!isfinite(o)) o = 0.f;
        if (resid) o += resid[row * (size_t)W + c];
        out[row * (size_t)W + c] = o;
    }
}

// RMSNorm writing bf16 hi/lo split (no residual; for GEMM A operands)
template <int W, int T>
__global__ void rmsnorm_split_k(const float* __restrict__ in,
                                const float* __restrict__ w,
                                bf16* __restrict__ ohi,
                                bf16* __restrict__ olo)
{
    constexpr int PER = W / T;
    const size_t row = blockIdx.x;
    const float* xr = in + row * (size_t)W;
    float vals[PER];
    float ss = 0.f;
#pragma unroll
    for (int i = 0; i < PER; i++) {
        float vv = xr[threadIdx.x + i * T];
        vv = fminf(fmaxf(vv, -10000.f), 10000.f);
        vals[i] = vv;
        ss += vv * vv;
    }
    __shared__ float red[T];
    red[threadIdx.x] = ss;
    __syncthreads();
#pragma unroll
    for (int s = T / 2; s > 0; s >>= 1) {
        if (threadIdx.x < s) red[threadIdx.x] += red[threadIdx.x + s];
        __syncthreads();
    }
    const float mean = red[0] / (float)W;
    const float inv = 1.f / sqrtf(fmaxf(mean, EPSV) + EPSV);
#pragma unroll
    for (int i = 0; i < PER; i++) {
        const int c = threadIdx.x + i * T;
        float o = vals[i] * inv * w[c];
        if (!isfinite(o)) o = 0.f;
        bf16 hi, lo;
        split_f32(o, hi, lo);
        ohi[row * (size_t)W + c] = hi;
        olo[row * (size_t)W + c] = lo;
    }
}

// ---------------------------------------------------------------------------
// Weight split: src [rows][K0] fp32 -> hi/lo [rows][KP] bf16 (zero pad)
// ---------------------------------------------------------------------------
__global__ void conv_split_k(const float* __restrict__ src,
                             bf16* __restrict__ hi, bf16* __restrict__ lo,
                             int rows, int K0, int KP)
{
    size_t idx = (size_t)blockIdx.x * blockDim.x + threadIdx.x;
    size_t n = (size_t)rows * KP;
    if (idx >= n) return;
    int r = (int)(idx / KP);
    int c = (int)(idx % KP);
    float v = (c < K0) ? src[(size_t)r * K0 + c] : 0.f;
    bf16 h, l;
    split_f32(v, h, l);
    hi[idx] = h;
    lo[idx] = l;
}

// ---------------------------------------------------------------------------
// silu(z1)*z3 with bf16 hi/lo split output (padded stride IIP)
// ---------------------------------------------------------------------------
__global__ void silu_split_k(const float* __restrict__ z1,
                             const float* __restrict__ z3,
                             bf16* __restrict__ ghi, bf16* __restrict__ glo)
{
    size_t idx = (size_t)blockIdx.x * blockDim.x + threadIdx.x;
    size_t n = (size_t)NROWS * IIP;
    if (idx >= n) return;
    int r = (int)(idx / IIP);
    int c = (int)(idx % IIP);
    float g = 0.f;
    if (c < II) {
        float a = z1[(size_t)r * II + c];
        float sv = a / (1.f + expf(-a));
        g = sv * z3[(size_t)r * II + c];
    }
    bf16 h, l;
    split_f32(g, h, l);
    ghi[idx] = h;
    glo[idx] = l;
}

// ---------------------------------------------------------------------------
// bf16x3 tensor-core GEMM (NT): C[n,m] = sum_k A[n,k]*B[m,k] + bias[m]
// A = Ah+Al (bf16 split of fp32), B = Bh+Bl. fp32 accumulate.
// CTA tile 128x128, BK=32, 256 threads (8 warps, 2x4), warp tile 64x32.
// cp.async double-buffered smem, pad-40 rows, ldmatrix fragments.
// K must be a multiple of 32. Output rows (N dim) multiple of 128.
// ---------------------------------------------------------------------------
#define SKT 40
#define STAGE_ELEMS (128 * SKT)                    // per array, bf16
#define GEMM_SMEM_BYTES (2 * 4 * STAGE_ELEMS * 2)  // 81920

__global__ void __launch_bounds__(256)
gemm_bf16x3(const bf16* __restrict__ Ah, const bf16* __restrict__ Al,
            const bf16* __restrict__ Bh, const bf16* __restrict__ Bl,
            const float* __restrict__ bias, float* __restrict__ C,
            int Mtot, int K, int ldc)
{
    extern __shared__ __align__(16) bf16 smem[];
    // layout: [stage][Ah | Al | Bh | Bl], each STAGE_ELEMS

    const int tid = threadIdx.x;
    const int lane = tid & 31;
    const int wid = tid >> 5;
    const int wm = wid & 1;   // warp row (M of output rows)
    const int wn = wid >> 1;  // warp col

    const int bm = blockIdx.x * 128;  // output col tile (weights dim)
    const int bn = blockIdx.y * 128;  // output row tile

    // global->smem loader mapping: thread t -> row t/2, 32B chunk (t&1)
    const int ldr = tid >> 1;
    const int ldcol = (tid & 1) * 16;   // bf16 col offset within BK

    const bf16* gAh = Ah + (size_t)(bn + ldr) * K + ldcol;
    const bf16* gAl = Al + (size_t)(bn + ldr) * K + ldcol;
    const bool bvalid = (bm + ldr) < Mtot;
    const bf16* gBh = Bh + (size_t)(bm + ldr) * K + ldcol;
    const bf16* gBl = Bl + (size_t)(bm + ldr) * K + ldcol;

    const int s_off = ldr * SKT + ldcol;

    float acc[4][4][4];
#pragma unroll
    for (int i = 0; i < 4; i++)
#pragma unroll
        for (int j = 0; j < 4; j++)
#pragma unroll
            for (int r = 0; r < 4; r++) acc[i][j][r] = 0.f;

    const int nk = K >> 5;   // BK=32 tiles

    // prologue: stage 0
    {
        bf16* s = smem;
        cpa16(s + 0 * STAGE_ELEMS + s_off,     gAh,     true);
        cpa16(s + 0 * STAGE_ELEMS + s_off + 8, gAh + 8, true);
        cpa16(s + 1 * STAGE_ELEMS + s_off,     gAl,     true);
        cpa16(s + 1 * STAGE_ELEMS + s_off + 8, gAl + 8, true);
        cpa16(s + 2 * STAGE_ELEMS + s_off,     gBh,     bvalid);
        cpa16(s + 2 * STAGE_ELEMS + s_off + 8, gBh + 8, bvalid);
        cpa16(s + 3 * STAGE_ELEMS + s_off,     gBl,     bvalid);
        cpa16(s + 3 * STAGE_ELEMS + s_off + 8, gBl + 8, bvalid);
    }
    cpa_commit();

    // fragment smem addresses (depend on lane only; add stage/mi/k offsets)
    const int a_row = wm * 64 + (lane & 15);          // + mi*16
    const int a_colsel = ((lane >> 4) & 1) << 3;      // 0 or 8
    const int b_row0 = wn * 32 + (((lane >> 4) & 1) << 3) + (lane & 7); // + pair*16
    const int b_colsel = ((lane >> 3) & 1) << 3;

    for (int kt = 0; kt < nk; kt++) {
        cpa_wait_all();
        __syncthreads();

        if (kt + 1 < nk) {
            bf16* s = smem + ((kt + 1) & 1) * (4 * STAGE_ELEMS);
            const int ko = (kt + 1) << 5;
            cpa16(s + 0 * STAGE_ELEMS + s_off,     gAh + ko,     true);
            cpa16(s + 0 * STAGE_ELEMS + s_off + 8, gAh + ko + 8, true);
            cpa16(s + 1 * STAGE_ELEMS + s_off,     gAl + ko,     true);
            cpa16(s + 1 * STAGE_ELEMS + s_off + 8, gAl + ko + 8, true);
            cpa16(s + 2 * STAGE_ELEMS + s_off,     gBh + ko,     bvalid);
            cpa16(s + 2 * STAGE_ELEMS + s_off + 8, gBh + ko + 8, bvalid);
            cpa16(s + 3 * STAGE_ELEMS + s_off,     gBl + ko,     bvalid);
            cpa16(s + 3 * STAGE_ELEMS + s_off + 8, gBl + ko + 8, bvalid);
        }
        cpa_commit();

        bf16* st = smem + (kt & 1) * (4 * STAGE_ELEMS);
        const uint32_t sAh = (uint32_t)__cvta_generic_to_shared(st + 0 * STAGE_ELEMS);
        const uint32_t sAl = (uint32_t)__cvta_generic_to_shared(st + 1 * STAGE_ELEMS);
        const uint32_t sBh = (uint32_t)__cvta_generic_to_shared(st + 2 * STAGE_ELEMS);
        const uint32_t sBl = (uint32_t)__cvta_generic_to_shared(st + 3 * STAGE_ELEMS);

#pragma unroll
        for (int ks = 0; ks < 2; ks++) {
            const int koff = ks * 16;
            uint32_t ah[4][4], al[4][4], bh[4][2], bl[4][2];
#pragma unroll
            for (int mi = 0; mi < 4; mi++) {
                const uint32_t off =
                    ((a_row + mi * 16) * SKT + koff + a_colsel) * 2;
                ldm4(ah[mi], sAh + off);
                ldm4(al[mi], sAl + off);
            }
#pragma unroll
            for (int p = 0; p < 2; p++) {
                const uint32_t off =
                    ((b_row0 + p * 16) * SKT + koff + b_colsel) * 2;
                uint32_t th[4], tl[4];
                ldm4(th, sBh + off);
                ldm4(tl, sBl + off);
                bh[p * 2][0] = th[0]; bh[p * 2][1] = th[1];
                bh[p * 2 + 1][0] = th[2]; bh[p * 2 + 1][1] = th[3];
                bl[p * 2][0] = tl[0]; bl[p * 2][1] = tl[1];
                bl[p * 2 + 1][0] = tl[2]; bl[p * 2 + 1][1] = tl[3];
            }
#pragma unroll
            for (int mi = 0; mi < 4; mi++)
#pragma unroll
                for (int ni = 0; ni < 4; ni++) {
                    mma16816(acc[mi][ni], ah[mi], bh[ni]);
                    mma16816(acc[mi][ni], ah[mi], bl[ni]);
                    mma16816(acc[mi][ni], al[mi], bh[ni]);
                }
        }
        __syncthreads();
    }

    // epilogue
    const int trow = lane >> 2;
    const int tcol = (lane & 3) * 2;
#pragma unroll
    for (int mi = 0; mi < 4; mi++) {
        const size_t r0 = (size_t)bn + wm * 64 + mi * 16 + trow;
#pragma unroll
        for (int ni = 0; ni < 4; ni++) {
            const int col = bm + wn * 32 + ni * 8 + tcol;
            if (col < Mtot) {
                const float b0 = bias[col];
                const float b1 = bias[col + 1];
                float2 v0 = make_float2(acc[mi][ni][0] + b0, acc[mi][ni][1] + b1);
                float2 v1 = make_float2(acc[mi][ni][2] + b0, acc[mi][ni][3] + b1);
                *(float2*)&C[r0 * (size_t)ldc + col] = v0;
                *(float2*)&C[(r0 + 8) * (size_t)ldc + col] = v1;
            }
        }
    }
}

// ---------------------------------------------------------------------------
// Tiled sliding-window attention (flash style), writes bf16 hi/lo split.
// ---------------------------------------------------------------------------
#define ATT_SMEM_FLOATS (4 * 64 * 64 + 3 * 64)

__global__ void __launch_bounds__(256)
attn_tile_kernel(const float* __restrict__ q, const float* __restrict__ k,
                 const float* __restrict__ v,
                 bf16* __restrict__ ohi, bf16* __restrict__ olo,
                 const int* __restrict__ winp)
{
    extern __shared__ float sm[];
    float* Qs  = sm;
    float* Kst = Qs + 64 * 64;
    float* Vs  = Kst + 64 * 64;
    float* Ss  = Vs + 64 * 64;
    float* m_s = Ss + 64 * 64;
    float* l_s = m_s + 64;
    float* sc_s = l_s + 64;

    const int q0 = blockIdx.x * 64;
    const int h  = blockIdx.y;
    const int b  = blockIdx.z;
    const int tid = threadIdx.x;
    const int win = *winp;

    const size_t base_q = ((size_t)(b * LL + q0)) * DD + h * HD;

    for (int i = tid; i < 1024; i += 256) {
        const int r = i >> 4;
        const int d4 = (i & 15) << 2;
        *(float4*)&Qs[r * 64 + d4] =
            *(const float4*)&q[base_q + (size_t)r * DD + d4];
    }
    if (tid < 64) { m_s[tid] = -INFINITY; l_s[tid] = 0.f; }

    const int ty = tid >> 4;
    const int tx = tid & 15;
    float accO[4][4];
#pragma unroll
    for (int i = 0; i < 4; i++)
#pragma unroll
        for (int j = 0; j < 4; j++) accO[i][j] = 0.f;

    int lo = q0 - win + 1;
    if (lo < 0) lo = 0;
    const int kt0 = lo >> 6;
    const int kt1 = q0 >> 6;

    __syncthreads();

    for (int kt = kt0; kt <= kt1; kt++) {
        const int j0 = kt << 6;
        const size_t base_k = ((size_t)(b * LL + j0)) * DD + h * HD;

        for (int i = tid; i < 1024; i += 256) {
            const int r = i >> 4;
            const int d4 = (i & 15) << 2;
            const float4 kv = *(const float4*)&k[base_k + (size_t)r * DD + d4];
            Kst[(d4 + 0) * 64 + r] = kv.x;
            Kst[(d4 + 1) * 64 + r] = kv.y;
            Kst[(d4 + 2) * 64 + r] = kv.z;
            Kst[(d4 + 3) * 64 + r] = kv.w;
            *(float4*)&Vs[r * 64 + d4] =
                *(const float4*)&v[base_k + (size_t)r * DD + d4];
        }
        __syncthreads();

        float accS[4][4];
#pragma unroll
        for (int i = 0; i < 4; i++)
#pragma unroll
            for (int j = 0; j < 4; j++) accS[i][j] = 0.f;

        for (int d = 0; d < 64; d += 4) {
            float4 qv[4];
#pragma unroll
            for (int i = 0; i < 4; i++)
                qv[i] = *(const float4*)&Qs[(ty * 4 + i) * 64 + d];
#pragma unroll
            for (int dd = 0; dd < 4; dd++) {
                const float4 kv = *(const float4*)&Kst[(d + dd) * 64 + tx * 4];
#pragma unroll
                for (int i = 0; i < 4; i++) {
                    const float qq = ((const float*)&qv[i])[dd];
                    accS[i][0] = fmaf(qq, kv.x, accS[i][0]);
                    accS[i][1] = fmaf(qq, kv.y, accS[i][1]);
                    accS[i][2] = fmaf(qq, kv.z, accS[i][2]);
                    accS[i][3] = fmaf(qq, kv.w, accS[i][3]);
                }
            }
        }

#pragma unroll
        for (int i = 0; i < 4; i++) {
            const int qi = q0 + ty * 4 + i;
#pragma unroll
            for (int j = 0; j < 4; j++) {
                const int jj = j0 + tx * 4 + j;
                const bool ok = (jj <= qi) && (qi - jj < win);
                Ss[(ty * 4 + i) * 64 + tx * 4 + j] =
                    ok ? accS[i][j] * 0.125f : -INFINITY;
            }
        }
        __syncthreads();

        {
            const int row = tid >> 2;
            const int part = tid & 3;
            float* srow = &Ss[row * 64 + part * 16];
            float tm = -INFINITY;
#pragma unroll
            for (int c = 0; c < 16; c++) tm = fmaxf(tm, srow[c]);
            tm = fmaxf(tm, __shfl_xor_sync(0xffffffffu, tm, 1));
            tm = fmaxf(tm, __shfl_xor_sync(0xffffffffu, tm, 2));

            const float mold = m_s[row];
            const float nm = fmaxf(mold, tm);
            float scale;
            float psum = 0.f;
            if (nm == -INFINITY) {
                scale = 1.f;
#pragma unroll
                for (int c = 0; c < 16; c++) srow[c] = 0.f;
            } else {
                scale = expf(mold - nm);
#pragma unroll
                for (int c = 0; c < 16; c++) {
                    const float p = expf(srow[c] - nm);
                    srow[c] = p;
                    psum += p;
                }
            }
            psum += __shfl_xor_sync(0xffffffffu, psum, 1);
            psum += __shfl_xor_sync(0xffffffffu, psum, 2);
            if (part == 0) {
                m_s[row] = nm;
                l_s[row] = l_s[row] * scale + psum;
                sc_s[row] = scale;
            }
        }
        __syncthreads();

#pragma unroll
        for (int i = 0; i < 4; i++) {
            const float s = sc_s[ty * 4 + i];
#pragma unroll
            for (int j = 0; j < 4; j++) accO[i][j] *= s;
        }
        for (int kk = 0; kk < 64; kk += 4) {
            float4 pv[4];
#pragma unroll
            for (int i = 0; i < 4; i++)
                pv[i] = *(const float4*)&Ss[(ty * 4 + i) * 64 + kk];
#pragma unroll
            for (int dd = 0; dd < 4; dd++) {
                const float4 vv = *(const float4*)&Vs[(kk + dd) * 64 + tx * 4];
#pragma unroll
                for (int i = 0; i < 4; i++) {
                    const float pp = ((const float*)&pv[i])[dd];
                    accO[i][0] = fmaf(pp, vv.x, accO[i][0]);
                    accO[i][1] = fmaf(pp, vv.y, accO[i][1]);
                    accO[i][2] = fmaf(pp, vv.z, accO[i][2]);
                    accO[i][3] = fmaf(pp, vv.w, accO[i][3]);
                }
            }
        }
        __syncthreads();
    }

#pragma unroll
    for (int i = 0; i < 4; i++) {
        const int r = ty * 4 + i;
        const float linv = 1.f / l_s[r];
#pragma unroll
        for (int j = 0; j < 4; j++) {
            float outv = accO[i][j] * linv;
            if (!isfinite(outv)) outv = 0.f;
            bf16 hi, lo2;
            split_f32(outv, hi, lo2);
            const size_t idx = ((size_t)(b * LL + q0 + r)) * DD + h * HD + tx * 4 + j;
            ohi[idx] = hi;
            olo[idx] = lo2;
        }
    }
}

// ---------------------------------------------------------------------------
// per-head rmsnorm for q/k (in-place, fp32)
// ---------------------------------------------------------------------------
// reuse rmsnorm_k<HD,64>

// ---------------------------------------------------------------------------
// Launch
// ---------------------------------------------------------------------------
extern "C" void kernel_launch(void* const* d_in, const int* in_sizes, int n_in,
                              void* d_out, int out_size)
{
    const float* x    = (const float*)d_in[0];
    const float* wq_w = (const float*)d_in[1];
    const float* wq_b = (const float*)d_in[2];
    const float* wk_w = (const float*)d_in[3];
    const float* wk_b = (const float*)d_in[4];
    const float* wv_w = (const float*)d_in[5];
    const float* wv_b = (const float*)d_in[6];
    const float* wo_w = (const float*)d_in[7];
    const float* wo_b = (const float*)d_in[8];
    const float* q_nw = (const float*)d_in[9];
    const float* k_nw = (const float*)d_in[10];
    const float* s_nw = (const float*)d_in[11];
    const float* sp_nw= (const float*)d_in[12];
    const float* f_nw = (const float*)d_in[13];
    const float* fp_nw= (const float*)d_in[14];
    const float* w1_w = (const float*)d_in[15];
    const float* w1_b = (const float*)d_in[16];
    const float* w2_w = (const float*)d_in[17];
    const float* w2_b = (const float*)d_in[18];
    const float* w3_w = (const float*)d_in[19];
    const float* w3_b = (const float*)d_in[20];
    const int*   winp = (const int*)d_in[21];

    float* fbase = nullptr;
    cudaGetSymbolAddress((void**)&fbase, g_scratch);
    float* q  = fbase + 0 * SZ_D;
    float* k  = fbase + 1 * SZ_D;
    float* v  = fbase + 2 * SZ_D;
    float* a  = fbase + 3 * SZ_D;
    float* h  = fbase + 4 * SZ_D;
    float* f  = fbase + 5 * SZ_D;
    float* z1 = fbase + 6 * SZ_D;
    float* z3 = fbase + 6 * SZ_D + SZ_I;

    bf16* bbase = nullptr;
    cudaGetSymbolAddress((void**)&bbase, g_bscratch);
    bf16* xn_h  = bbase + 0 * BSZ_ACT;
    bf16* xn_l  = bbase + 1 * BSZ_ACT;
    bf16* at_h  = bbase + 2 * BSZ_ACT;
    bf16* at_l  = bbase + 3 * BSZ_ACT;
    bf16* hn_h  = bbase + 4 * BSZ_ACT;
    bf16* hn_l  = bbase + 5 * BSZ_ACT;
    bf16* g_h   = bbase + 6 * BSZ_ACT;
    bf16* g_l   = bbase + 6 * BSZ_ACT + BSZ_G;
    bf16* w_h   = bbase + 6 * BSZ_ACT + 2 * BSZ_G;
    bf16* w_l   = bbase + 6 * BSZ_ACT + 2 * BSZ_G + BSZ_W;

    float* out = (float*)d_out;

    cudaFuncSetAttribute(gemm_bf16x3,
                         cudaFuncAttributeMaxDynamicSharedMemorySize,
                         GEMM_SMEM_BYTES);

    // 1) xn = rmsnorm(x, seq_norm_w) -> bf16 split
    rmsnorm_split_k<DD, 256><<<NROWS, 256>>>(x, s_nw, xn_h, xn_l);

    // 2) QKV projections (bf16x3 tensor GEMM)
    {
        dim3 grid(DD / 128, NROWS / 128);
        const int wthreads = 256;
        const int wN = DD * DD;
        const int wblocks = (wN + wthreads - 1) / wthreads;

        conv_split_k<<<wblocks, wthreads>>>(wq_w, w_h, w_l, DD, DD, DD);
        gemm_bf16x3<<<grid, 256, GEMM_SMEM_BYTES>>>(xn_h, xn_l, w_h, w_l, wq_b, q, DD, DD, DD);
        conv_split_k<<<wblocks, wthreads>>>(wk_w, w_h, w_l, DD, DD, DD);
        gemm_bf16x3<<<grid, 256, GEMM_SMEM_BYTES>>>(xn_h, xn_l, w_h, w_l, wk_b, k, DD, DD, DD);
        conv_split_k<<<wblocks, wthreads>>>(wv_w, w_h, w_l, DD, DD, DD);
        gemm_bf16x3<<<grid, 256, GEMM_SMEM_BYTES>>>(xn_h, xn_l, w_h, w_l, wv_b, v, DD, DD, DD);
    }

    // 3) per-head q/k rmsnorm (fp32, in-place)
    rmsnorm_k<HD, 64><<<NROWS * HH, 64>>>(q, q_nw, nullptr, q);
    rmsnorm_k<HD, 64><<<NROWS * HH, 64>>>(k, k_nw, nullptr, k);

    // 4) attention -> bf16 split output
    {
        const size_t smem_bytes = (size_t)ATT_SMEM_FLOATS * sizeof(float);
        cudaFuncSetAttribute(attn_tile_kernel,
                             cudaFuncAttributeMaxDynamicSharedMemorySize,
                             (int)smem_bytes);
        dim3 grid(LL / 64, HH, BB);
        attn_tile_kernel<<<grid, 256, smem_bytes>>>(q, k, v, at_h, at_l, winp);
    }

    // 5) output projection
    {
        dim3 grid(DD / 128, NROWS / 128);
        const int wN = DD * DD;
        conv_split_k<<<(wN + 255) / 256, 256>>>(wo_w, w_h, w_l, DD, DD, DD);
        gemm_bf16x3<<<grid, 256, GEMM_SMEM_BYTES>>>(at_h, at_l, w_h, w_l, wo_b, a, DD, DD, DD);
    }

    // 6) h = x + rmsnorm(a, seq_post_norm_w)
    rmsnorm_k<DD, 256><<<NROWS, 256>>>(a, sp_nw, x, h);

    // 7) hn = rmsnorm(h, ffn_norm_w) -> bf16 split
    rmsnorm_split_k<DD, 256><<<NROWS, 256>>>(h, f_nw, hn_h, hn_l);

    // 8) z1/z3 GEMMs
    {
        dim3 grid((II + 127) / 128, NROWS / 128);
        const int wN = II * DD;
        conv_split_k<<<(wN + 255) / 256, 256>>>(w1_w, w_h, w_l, II, DD, DD);
        gemm_bf16x3<<<grid, 256, GEMM_SMEM_BYTES>>>(hn_h, hn_l, w_h, w_l, w1_b, z1, II, DD, II);
        conv_split_k<<<(wN + 255) / 256, 256>>>(w3_w, w_h, w_l, II, DD, DD);
        gemm_bf16x3<<<grid, 256, GEMM_SMEM_BYTES>>>(hn_h, hn_l, w_h, w_l, w3_b, z3, II, DD, II);
    }

    // 9) g = silu(z1)*z3 -> bf16 split (padded K=IIP)
    {
        size_t n = (size_t)NROWS * IIP;
        silu_split_k<<<(int)((n + 255) / 256), 256>>>(z1, z3, g_h, g_l);
    }

    // 10) f = g @ w2^T + b2   (K = IIP with zero pad)
    {
        dim3 grid(DD / 128, NROWS / 128);
        const size_t wN = (size_t)DD * IIP;
        conv_split_k<<<(int)((wN + 255) / 256), 256>>>(w2_w, w_h, w_l, DD, II, IIP);
        gemm_bf16x3<<<grid, 256, GEMM_SMEM_BYTES>>>(g_h, g_l, w_h, w_l, w2_b, f, DD, IIP, DD);
    }

    // 11) out = h + rmsnorm(f, ffn_post_norm_w)
    rmsnorm_k<DD, 256><<<NROWS, 256>>>(f, fp_nw, h, out);
}